// round 1
// baseline (speedup 1.0000x reference)
#include <cuda_runtime.h>
#include <cuda_bf16.h>

// ---------------------------------------------------------------------------
// DigitConvolutionalModel: out = relu((conv3x3(x))·fc1ᵀ + b1)·fc2ᵀ + b2
// Folded:                  out = relu(x·W1effᵀ + b1)·fc2ᵀ + b2
//   W1eff[n][k] = sum_{i,j} fc1_w[n][r*26+c]*conv_w[i][j], k=(r+i)*28+(c+j)
// ---------------------------------------------------------------------------

#define MT 128   // rows per block
#define KC 32    // K chunk
#define NT 128   // padded hidden dim (100 -> 128)

// Effective fc1 weights, transposed: g_w1t[k][n], k<784, n<128 (n>=100 zero)
__device__ float g_w1t[784 * 128];

__global__ void build_w1t(const float* __restrict__ conv_w,
                          const float* __restrict__ fc1_w) {
    int idx = blockIdx.x * blockDim.x + threadIdx.x;
    if (idx >= 784 * 128) return;
    int n = idx & 127;
    int k = idx >> 7;
    float v = 0.f;
    if (n < 100) {
        int y  = k / 28;
        int xx = k % 28;
        #pragma unroll
        for (int i = 0; i < 3; i++) {
            int r = y - i;
            if (r < 0 || r > 25) continue;
            #pragma unroll
            for (int j = 0; j < 3; j++) {
                int c = xx - j;
                if (c < 0 || c > 25) continue;
                v += fc1_w[n * 676 + r * 26 + c] * conv_w[i * 3 + j];
            }
        }
    }
    g_w1t[k * 128 + n] = v;
}

__global__ __launch_bounds__(256, 2)
void fused_mlp(const float* __restrict__ x,
               const float* __restrict__ fc1_b,
               const float* __restrict__ fc2_w,
               const float* __restrict__ fc2_b,
               float* __restrict__ out, int Brows) {
    // A staged transposed: As[k][m], 132 stride (16B aligned rows, fewer conflicts)
    __shared__ float As[KC][132];
    __shared__ float Bs[KC][128];
    __shared__ float b1s[100];
    __shared__ float w2s[10 * 100];
    __shared__ float b2s[10];

    const int tid = threadIdx.x;
    const int tx = tid & 15;       // column group
    const int ty = tid >> 4;       // row group
    const int m0 = blockIdx.x * MT;

    if (tid < 100) b1s[tid] = fc1_b[tid];
    if (tid < 10)  b2s[tid] = fc2_b[tid];
    for (int i = tid; i < 1000; i += 256) w2s[i] = fc2_w[i];

    float acc[8][8];
    #pragma unroll
    for (int i = 0; i < 8; i++)
        #pragma unroll
        for (int j = 0; j < 8; j++) acc[i][j] = 0.f;

    for (int k0 = 0; k0 < 784; k0 += KC) {
        __syncthreads();
        // ---- stage A tile (transpose x[m][k] -> As[k][m]), vectorized float4
        #pragma unroll
        for (int i = 0; i < 4; i++) {
            int idx4 = tid + i * 256;         // 1024 float4 total
            int m  = idx4 >> 3;               // 0..127
            int k4 = idx4 & 7;                // 0..7 (each covers 4 k)
            int kg = k0 + k4 * 4;
            int row = m0 + m;
            float4 v = make_float4(0.f, 0.f, 0.f, 0.f);
            if (kg < 784 && row < Brows)
                v = *reinterpret_cast<const float4*>(&x[(size_t)row * 784 + kg]);
            As[k4 * 4 + 0][m] = v.x;
            As[k4 * 4 + 1][m] = v.y;
            As[k4 * 4 + 2][m] = v.z;
            As[k4 * 4 + 3][m] = v.w;
        }
        // ---- stage B tile (already [k][n] in global, coalesced copy)
        #pragma unroll
        for (int i = 0; i < 16; i++) {
            int idx = tid + i * 256;          // 4096 floats
            int k = idx >> 7;
            int n = idx & 127;
            int kg = k0 + k;
            Bs[k][n] = (kg < 784) ? g_w1t[kg * 128 + n] : 0.f;
        }
        __syncthreads();
        // ---- 8x8 microtile mainloop
        #pragma unroll
        for (int k = 0; k < KC; k++) {
            float a[8], b[8];
            *reinterpret_cast<float4*>(a)     = *reinterpret_cast<const float4*>(&As[k][ty * 4]);
            *reinterpret_cast<float4*>(a + 4) = *reinterpret_cast<const float4*>(&As[k][64 + ty * 4]);
            *reinterpret_cast<float4*>(b)     = *reinterpret_cast<const float4*>(&Bs[k][tx * 4]);
            *reinterpret_cast<float4*>(b + 4) = *reinterpret_cast<const float4*>(&Bs[k][64 + tx * 4]);
            #pragma unroll
            for (int i = 0; i < 8; i++)
                #pragma unroll
                for (int j = 0; j < 8; j++)
                    acc[i][j] = fmaf(a[i], b[j], acc[i][j]);
        }
    }

    // ---- fused epilogue: h = relu(acc + b1); out = h·fc2ᵀ + b2
    // Each thread reduces its 8 hidden cols into 10 partials per row, then
    // butterfly-shuffle over the 16 tx lanes (lane bits 0..3 == tx).
    #pragma unroll
    for (int ri = 0; ri < 8; ri++) {
        int mrow = (ri < 4) ? (ty * 4 + ri) : (64 + ty * 4 + (ri - 4));
        float p[10];
        #pragma unroll
        for (int j = 0; j < 10; j++) p[j] = 0.f;
        #pragma unroll
        for (int ci = 0; ci < 8; ci++) {
            int n = (ci < 4) ? (tx * 4 + ci) : (64 + tx * 4 + (ci - 4));
            if (n < 100) {
                float h = acc[ri][ci] + b1s[n];
                h = fmaxf(h, 0.f);
                #pragma unroll
                for (int j = 0; j < 10; j++)
                    p[j] = fmaf(h, w2s[j * 100 + n], p[j]);
            }
        }
        #pragma unroll
        for (int mask = 8; mask >= 1; mask >>= 1) {
            #pragma unroll
            for (int j = 0; j < 10; j++)
                p[j] += __shfl_xor_sync(0xffffffffu, p[j], mask);
        }
        if (tx == 0) {
            int row = m0 + mrow;
            if (row < Brows) {
                #pragma unroll
                for (int j = 0; j < 10; j++)
                    out[(size_t)row * 10 + j] = p[j] + b2s[j];
            }
        }
    }
}

extern "C" void kernel_launch(void* const* d_in, const int* in_sizes, int n_in,
                              void* d_out, int out_size) {
    const float* x      = (const float*)d_in[0];
    const float* conv_w = (const float*)d_in[1];
    const float* fc1_w  = (const float*)d_in[2];
    const float* fc1_b  = (const float*)d_in[3];
    const float* fc2_w  = (const float*)d_in[4];
    const float* fc2_b  = (const float*)d_in[5];
    float* out = (float*)d_out;

    int Brows = in_sizes[0] / 784;

    build_w1t<<<(784 * 128 + 255) / 256, 256>>>(conv_w, fc1_w);

    int grid = (Brows + MT - 1) / MT;
    fused_mlp<<<grid, 256>>>(x, fc1_b, fc2_w, fc2_b, out, Brows);
}

// round 5
// speedup vs baseline: 4.1273x; 4.1273x over previous
#include <cuda_runtime.h>
#include <cuda_fp16.h>
#include <cstdint>

// ---------------------------------------------------------------------------
// out = relu(x·W1effᵀ + b1)·fc2ᵀ + b2   via mma.sync m16n8k16 (fp16 in, fp32 acc)
//   W1eff[n][k] = sum_{i,j} fc1_w[n][r*26+c]*conv_w[i][j]  (conv folded)
// GEMM: M=65536 (128/CTA), N=104 (100 used, 13 n-tiles), K=784 pad 832 (13x64)
// ---------------------------------------------------------------------------

#define KPAD   832
#define NCHUNK 13
#define KC     64
#define SAS    72      // smem row stride in halves (bank-conflict-free)
#define NTILES 13      // 13 * 8 = 104 >= 100 hidden units

// Precomputed effective fc1 weights, fp16, K-major: g_w1[n][k], zero padded.
__device__ __half g_w1[128 * KPAD];

// ---------------- weight fold + fp16 conversion ----------------------------

__global__ void build_w1(const float* __restrict__ conv_w,
                         const float* __restrict__ fc1_w) {
    int idx = blockIdx.x * blockDim.x + threadIdx.x;
    if (idx >= 128 * KPAD) return;
    int n = idx / KPAD;
    int k = idx % KPAD;
    float v = 0.f;
    if (n < 100 && k < 784) {
        int y  = k / 28;
        int xx = k % 28;
        #pragma unroll
        for (int i = 0; i < 3; i++) {
            int r = y - i;
            if (r < 0 || r > 25) continue;
            #pragma unroll
            for (int j = 0; j < 3; j++) {
                int c = xx - j;
                if (c < 0 || c > 25) continue;
                v += fc1_w[n * 676 + r * 26 + c] * conv_w[i * 3 + j];
            }
        }
    }
    g_w1[n * KPAD + k] = __float2half(v);
}

// ---------------- fused GEMM + epilogue ------------------------------------

__device__ __forceinline__ void mma16816(float& c0, float& c1, float& c2, float& c3,
                                         uint32_t a0, uint32_t a1, uint32_t a2, uint32_t a3,
                                         uint32_t b0, uint32_t b1) {
    asm volatile(
        "mma.sync.aligned.m16n8k16.row.col.f32.f16.f16.f32 "
        "{%0,%1,%2,%3}, {%4,%5,%6,%7}, {%8,%9}, {%0,%1,%2,%3};"
        : "+f"(c0), "+f"(c1), "+f"(c2), "+f"(c3)
        : "r"(a0), "r"(a1), "r"(a2), "r"(a3), "r"(b0), "r"(b1));
}

__global__ __launch_bounds__(256, 2)
void fused_gemm(const float* __restrict__ x,
                const float* __restrict__ fc1_b,
                const float* __restrict__ fc2_w,
                const float* __restrict__ fc2_b,
                float* __restrict__ out, int Brows) {
    __shared__ __half sA[128 * SAS];   // x tile   [m][k], 18KB
    __shared__ __half sB[128 * SAS];   // w1 tile  [n][k], 18KB
    __shared__ float b1s[128];
    __shared__ float w2s[100][12];     // [n][j], j<10 used (pad 12 vs bank)
    __shared__ float b2s[16];

    const int tid = threadIdx.x;
    const int wid = tid >> 5;
    const int lid = tid & 31;
    const int qid = lid & 3;           // quad lane
    const int qrow = lid >> 2;         // 0..7
    const int m0 = blockIdx.x * 128;
    const int mw = wid * 16;           // warp's row base within tile

    if (tid < 128) b1s[tid] = (tid < 100) ? fc1_b[tid] : 0.f;
    if (tid < 100) {
        #pragma unroll
        for (int j = 0; j < 10; j++) w2s[tid][j] = fc2_w[j * 100 + tid];
    }
    if (tid < 10) b2s[tid] = fc2_b[tid];

    float c[NTILES][4];
    #pragma unroll
    for (int t = 0; t < NTILES; t++)
        #pragma unroll
        for (int q = 0; q < 4; q++) c[t][q] = 0.f;

    for (int ch = 0; ch < NCHUNK; ch++) {
        const int kg0 = ch * KC;
        __syncthreads();   // previous chunk fully consumed

        // ---- stage A: x[m0+m][kg0+..] fp32 -> fp16, 2048 float4 / 8 per thr
        #pragma unroll
        for (int i = 0; i < 8; i++) {
            int idx = tid + i * 256;
            int m  = idx >> 4;             // 0..127
            int kq = idx & 15;             // float4 slot in 64-k chunk
            int row = m0 + m;
            int kg  = kg0 + kq * 4;
            float4 v = make_float4(0.f, 0.f, 0.f, 0.f);
            if (row < Brows && kg < 784)
                v = *reinterpret_cast<const float4*>(&x[(size_t)row * 784 + kg]);
            __half2 h01 = __floats2half2_rn(v.x, v.y);
            __half2 h23 = __floats2half2_rn(v.z, v.w);
            *reinterpret_cast<uint2*>(&sA[m * SAS + kq * 4]) =
                make_uint2(*reinterpret_cast<uint32_t*>(&h01),
                           *reinterpret_cast<uint32_t*>(&h23));
        }

        // ---- stage B: g_w1[n][kg0+..] fp16, 1024 uint4 / 4 per thread
        #pragma unroll
        for (int i = 0; i < 4; i++) {
            int idx = tid + i * 256;
            int n  = idx >> 3;             // 0..127
            int k8 = idx & 7;              // 8-half group
            uint4 v = *reinterpret_cast<const uint4*>(&g_w1[n * KPAD + kg0 + k8 * 8]);
            *reinterpret_cast<uint4*>(&sB[n * SAS + k8 * 8]) = v;
        }
        __syncthreads();

        // ---- 4 k-steps of 16
        #pragma unroll
        for (int ks = 0; ks < 4; ks++) {
            const int kb = ks * 16 + qid * 2;
            const int ar = (mw + qrow) * SAS + kb;
            uint32_t a0 = *reinterpret_cast<const uint32_t*>(&sA[ar]);
            uint32_t a1 = *reinterpret_cast<const uint32_t*>(&sA[ar + 8 * SAS]);
            uint32_t a2 = *reinterpret_cast<const uint32_t*>(&sA[ar + 8]);
            uint32_t a3 = *reinterpret_cast<const uint32_t*>(&sA[ar + 8 * SAS + 8]);
            #pragma unroll
            for (int t = 0; t < NTILES; t++) {
                const int br = (t * 8 + qrow) * SAS + kb;
                uint32_t b0 = *reinterpret_cast<const uint32_t*>(&sB[br]);
                uint32_t b1 = *reinterpret_cast<const uint32_t*>(&sB[br + 8]);
                mma16816(c[t][0], c[t][1], c[t][2], c[t][3],
                         a0, a1, a2, a3, b0, b1);
            }
        }
    }

    // ---- epilogue: h = relu(c + b1); p = h·fc2ᵀ; quad-reduce; + b2; store
    // Thread owns rows (mw+qrow, mw+qrow+8), cols t*8 + qid*2 + {0,1}.
    float p0[10], p1[10];
    #pragma unroll
    for (int j = 0; j < 10; j++) { p0[j] = 0.f; p1[j] = 0.f; }

    #pragma unroll
    for (int t = 0; t < NTILES; t++) {
        #pragma unroll
        for (int e = 0; e < 2; e++) {
            int n = t * 8 + qid * 2 + e;
            if (n < 100) {
                float h0 = fmaxf(c[t][0 + e] + b1s[n], 0.f);  // row qrow
                float h1 = fmaxf(c[t][2 + e] + b1s[n], 0.f);  // row qrow+8
                #pragma unroll
                for (int j = 0; j < 10; j++) {
                    p0[j] = fmaf(h0, w2s[n][j], p0[j]);
                    p1[j] = fmaf(h1, w2s[n][j], p1[j]);
                }
            }
        }
    }
    #pragma unroll
    for (int mask = 2; mask >= 1; mask >>= 1) {
        #pragma unroll
        for (int j = 0; j < 10; j++) {
            p0[j] += __shfl_xor_sync(0xffffffffu, p0[j], mask);
            p1[j] += __shfl_xor_sync(0xffffffffu, p1[j], mask);
        }
    }
    if (qid == 0) {
        int row0 = m0 + mw + qrow;
        int row1 = row0 + 8;
        if (row0 < Brows) {
            #pragma unroll
            for (int j = 0; j < 10; j++)
                out[(size_t)row0 * 10 + j] = p0[j] + b2s[j];
        }
        if (row1 < Brows) {
            #pragma unroll
            for (int j = 0; j < 10; j++)
                out[(size_t)row1 * 10 + j] = p1[j] + b2s[j];
        }
    }
}

// ---------------- launch ---------------------------------------------------

extern "C" void kernel_launch(void* const* d_in, const int* in_sizes, int n_in,
                              void* d_out, int out_size) {
    const float* x      = (const float*)d_in[0];
    const float* conv_w = (const float*)d_in[1];
    const float* fc1_w  = (const float*)d_in[2];
    const float* fc1_b  = (const float*)d_in[3];
    const float* fc2_w  = (const float*)d_in[4];
    const float* fc2_b  = (const float*)d_in[5];
    float* out = (float*)d_out;

    int Brows = in_sizes[0] / 784;

    build_w1<<<(128 * KPAD + 255) / 256, 256>>>(conv_w, fc1_w);

    int grid = (Brows + 127) / 128;
    fused_gemm<<<grid, 256>>>(x, fc1_b, fc2_w, fc2_b, out, Brows);
}

// round 6
// speedup vs baseline: 4.4747x; 1.0842x over previous
#include <cuda_runtime.h>
#include <cuda_fp16.h>
#include <cstdint>

// ---------------------------------------------------------------------------
// out = relu(x·W1effᵀ + b1)·fc2ᵀ + b2   via mma.sync m16n8k16 (fp16 in, fp32 acc)
// Double-buffered pipeline: LDG/cp.async(c+1) -> MMA(c) -> STS(c+1) -> sync
// GEMM: M=65536 (128/CTA), N=104 (13 n-tiles), K=784 pad 832 (13 chunks x 64)
// ---------------------------------------------------------------------------

#define KPAD    832
#define NCHUNK  13
#define NTILES  13
#define ATILE_B 16384   // 128 rows * 128 bytes (64 halves, XOR-swizzled)
#define BTILE_B 16384

__device__ __half g_w1[128 * KPAD];

// ---------------- weight fold + fp16 conversion ----------------------------

__global__ void build_w1(const float* __restrict__ conv_w,
                         const float* __restrict__ fc1_w) {
    int idx = blockIdx.x * blockDim.x + threadIdx.x;
    if (idx >= 128 * KPAD) return;
    int n = idx / KPAD;
    int k = idx % KPAD;
    float v = 0.f;
    if (n < 100 && k < 784) {
        int y  = k / 28;
        int xx = k % 28;
        #pragma unroll
        for (int i = 0; i < 3; i++) {
            int r = y - i;
            if (r < 0 || r > 25) continue;
            #pragma unroll
            for (int j = 0; j < 3; j++) {
                int c = xx - j;
                if (c < 0 || c > 25) continue;
                v += fc1_w[n * 676 + r * 26 + c] * conv_w[i * 3 + j];
            }
        }
    }
    g_w1[n * KPAD + k] = __float2half(v);
}

// ---------------- PTX helpers ----------------------------------------------

__device__ __forceinline__ uint32_t smem_u32(const void* p) {
    uint32_t a;
    asm("{ .reg .u64 t; cvta.to.shared.u64 t, %1; cvt.u32.u64 %0, t; }"
        : "=r"(a) : "l"(p));
    return a;
}

__device__ __forceinline__ void ldsm_x4(uint32_t& r0, uint32_t& r1,
                                        uint32_t& r2, uint32_t& r3, uint32_t addr) {
    asm volatile("ldmatrix.sync.aligned.m8n8.x4.shared.b16 {%0,%1,%2,%3}, [%4];"
        : "=r"(r0), "=r"(r1), "=r"(r2), "=r"(r3) : "r"(addr));
}

__device__ __forceinline__ void ldsm_x2(uint32_t& r0, uint32_t& r1, uint32_t addr) {
    asm volatile("ldmatrix.sync.aligned.m8n8.x2.shared.b16 {%0,%1}, [%2];"
        : "=r"(r0), "=r"(r1) : "r"(addr));
}

__device__ __forceinline__ void mma16816(float* c,
                                         uint32_t a0, uint32_t a1, uint32_t a2, uint32_t a3,
                                         uint32_t b0, uint32_t b1) {
    asm volatile(
        "mma.sync.aligned.m16n8k16.row.col.f32.f16.f16.f32 "
        "{%0,%1,%2,%3}, {%4,%5,%6,%7}, {%8,%9}, {%0,%1,%2,%3};"
        : "+f"(c[0]), "+f"(c[1]), "+f"(c[2]), "+f"(c[3])
        : "r"(a0), "r"(a1), "r"(a2), "r"(a3), "r"(b0), "r"(b1));
}

// ---------------- staging helpers ------------------------------------------

// B tile: g_w1[n][ch*64 .. +63] -> smem, XOR-swizzled 128B rows, via cp.async
__device__ __forceinline__ void stage_b_async(uint32_t bbuf, int ch, int tid) {
    #pragma unroll
    for (int i = 0; i < 4; i++) {
        int idx = tid + i * 256;
        int n  = idx >> 3;
        int k8 = idx & 7;
        uint32_t dst = bbuf + n * 128 + ((k8 ^ (n & 7)) << 4);
        const __half* s = &g_w1[n * KPAD + ch * 64 + k8 * 8];
        asm volatile("cp.async.cg.shared.global [%0], [%1], 16;"
                     :: "r"(dst), "l"(s) : "memory");
    }
    asm volatile("cp.async.commit_group;" ::: "memory");
}

// A prefetch: x[m0+m][ch*64 + kq*4 ..] fp32 -> registers (zero-padded)
__device__ __forceinline__ void load_a(const float* __restrict__ x, int m0,
                                       int Brows, int ch, int tid, float4* av) {
    #pragma unroll
    for (int i = 0; i < 8; i++) {
        int idx = tid + i * 256;
        int m  = idx >> 4;
        int kq = idx & 15;
        int row = m0 + m;
        int kg  = ch * 64 + kq * 4;
        float4 v = make_float4(0.f, 0.f, 0.f, 0.f);
        if (row < Brows && kg < 784)
            v = *reinterpret_cast<const float4*>(&x[(size_t)row * 784 + kg]);
        av[i] = v;
    }
}

// A store: convert fp32 regs -> fp16, XOR-swizzled STS
__device__ __forceinline__ void store_a(uint32_t abuf, int tid, const float4* av) {
    #pragma unroll
    for (int i = 0; i < 8; i++) {
        int idx = tid + i * 256;
        int m  = idx >> 4;
        int kq = idx & 15;
        __half2 h01 = __floats2half2_rn(av[i].x, av[i].y);
        __half2 h23 = __floats2half2_rn(av[i].z, av[i].w);
        uint32_t u01 = *reinterpret_cast<const uint32_t*>(&h01);
        uint32_t u23 = *reinterpret_cast<const uint32_t*>(&h23);
        uint32_t dst = abuf + m * 128 + (((kq >> 1) ^ (m & 7)) << 4) + (kq & 1) * 8;
        asm volatile("st.shared.v2.b32 [%0], {%1,%2};"
                     :: "r"(dst), "r"(u01), "r"(u23) : "memory");
    }
}

// ---------------- fused GEMM + epilogue ------------------------------------

__global__ __launch_bounds__(256, 2)
void fused_gemm(const float* __restrict__ x,
                const float* __restrict__ fc1_b,
                const float* __restrict__ fc2_w,
                const float* __restrict__ fc2_b,
                float* __restrict__ out, int Brows) {
    extern __shared__ __align__(128) uint8_t dynsmem[];
    __shared__ float b1s[128];
    __shared__ float w2s[100][12];
    __shared__ float b2v[16];

    const int tid = threadIdx.x;
    const int wid = tid >> 5;
    const int lid = tid & 31;
    const int qid = lid & 3;
    const int qrow = lid >> 2;
    const int m0 = blockIdx.x * 128;
    const int mw = wid * 16;

    const uint32_t sbase = smem_u32(dynsmem);
    const uint32_t aB[2] = { sbase, sbase + ATILE_B };
    const uint32_t bB[2] = { sbase + 2 * ATILE_B, sbase + 2 * ATILE_B + BTILE_B };

    // ldmatrix lane geometry
    const int a_m  = mw + (lid & 15);
    const int a_ko = lid >> 4;                          // 0/1 -> k chunk half
    const int b_nl = ((lid >> 4) & 1) * 8 + (lid & 7);  // within n-pair
    const int b_ko = (lid >> 3) & 1;
    const int b2_n = 96 + (lid & 7);                    // last tile (x2)

    if (tid < 128) b1s[tid] = (tid < 100) ? fc1_b[tid] : 0.f;
    if (tid < 100) {
        #pragma unroll
        for (int j = 0; j < 10; j++) w2s[tid][j] = fc2_w[j * 100 + tid];
    }
    if (tid < 10) b2v[tid] = fc2_b[tid];

    float c[NTILES][4];
    #pragma unroll
    for (int t = 0; t < NTILES; t++)
        #pragma unroll
        for (int q = 0; q < 4; q++) c[t][q] = 0.f;

    float4 av[8];

    // ---- prologue: stage chunk 0
    stage_b_async(bB[0], 0, tid);
    load_a(x, m0, Brows, 0, tid, av);
    store_a(aB[0], tid, av);
    asm volatile("cp.async.wait_group 0;" ::: "memory");
    __syncthreads();

    // ---- pipelined mainloop
    for (int ch = 0; ch < NCHUNK; ch++) {
        const int cur = ch & 1;

        if (ch + 1 < NCHUNK) {
            stage_b_async(bB[cur ^ 1], ch + 1, tid);
            load_a(x, m0, Brows, ch + 1, tid, av);
        }

        // MMA phase on buffers[cur]
        #pragma unroll
        for (int ks = 0; ks < 4; ks++) {
            uint32_t a0, a1, a2, a3;
            uint32_t aaddr = aB[cur] + a_m * 128 + (((ks * 2 + a_ko) ^ (a_m & 7)) << 4);
            ldsm_x4(a0, a1, a2, a3, aaddr);
            #pragma unroll
            for (int tp = 0; tp < 6; tp++) {
                int n_l = tp * 16 + b_nl;
                uint32_t baddr = bB[cur] + n_l * 128 + (((ks * 2 + b_ko) ^ (n_l & 7)) << 4);
                uint32_t f0, f1, f2, f3;
                ldsm_x4(f0, f1, f2, f3, baddr);
                mma16816(c[tp * 2],     a0, a1, a2, a3, f0, f1);
                mma16816(c[tp * 2 + 1], a0, a1, a2, a3, f2, f3);
            }
            {
                int n_l = b2_n;
                uint32_t baddr = bB[cur] + n_l * 128 + (((ks * 2 + b_ko) ^ (n_l & 7)) << 4);
                uint32_t f0, f1;
                ldsm_x2(f0, f1, baddr);
                mma16816(c[12], a0, a1, a2, a3, f0, f1);
            }
        }

        if (ch + 1 < NCHUNK) {
            store_a(aB[cur ^ 1], tid, av);
            asm volatile("cp.async.wait_group 0;" ::: "memory");
        }
        __syncthreads();
    }

    // ---- epilogue: h = relu(c + b1); p = h·fc2ᵀ; quad-reduce; + b2; store
    float p0[10], p1[10];
    #pragma unroll
    for (int j = 0; j < 10; j++) { p0[j] = 0.f; p1[j] = 0.f; }

    #pragma unroll
    for (int t = 0; t < NTILES; t++) {
        #pragma unroll
        for (int e = 0; e < 2; e++) {
            int n = t * 8 + qid * 2 + e;
            if (n < 100) {
                float h0 = fmaxf(c[t][0 + e] + b1s[n], 0.f);  // row qrow
                float h1 = fmaxf(c[t][2 + e] + b1s[n], 0.f);  // row qrow+8
                #pragma unroll
                for (int j = 0; j < 10; j++) {
                    p0[j] = fmaf(h0, w2s[n][j], p0[j]);
                    p1[j] = fmaf(h1, w2s[n][j], p1[j]);
                }
            }
        }
    }
    #pragma unroll
    for (int mask = 2; mask >= 1; mask >>= 1) {
        #pragma unroll
        for (int j = 0; j < 10; j++) {
            p0[j] += __shfl_xor_sync(0xffffffffu, p0[j], mask);
            p1[j] += __shfl_xor_sync(0xffffffffu, p1[j], mask);
        }
    }
    if (qid == 0) {
        int row0 = m0 + mw + qrow;
        int row1 = row0 + 8;
        if (row0 < Brows) {
            #pragma unroll
            for (int j = 0; j < 10; j++)
                out[(size_t)row0 * 10 + j] = p0[j] + b2v[j];
        }
        if (row1 < Brows) {
            #pragma unroll
            for (int j = 0; j < 10; j++)
                out[(size_t)row1 * 10 + j] = p1[j] + b2v[j];
        }
    }
}

// ---------------- launch ---------------------------------------------------

extern "C" void kernel_launch(void* const* d_in, const int* in_sizes, int n_in,
                              void* d_out, int out_size) {
    const float* x      = (const float*)d_in[0];
    const float* conv_w = (const float*)d_in[1];
    const float* fc1_w  = (const float*)d_in[2];
    const float* fc1_b  = (const float*)d_in[3];
    const float* fc2_w  = (const float*)d_in[4];
    const float* fc2_b  = (const float*)d_in[5];
    float* out = (float*)d_out;

    int Brows = in_sizes[0] / 784;

    build_w1<<<(128 * KPAD + 255) / 256, 256>>>(conv_w, fc1_w);

    const int smem_bytes = 2 * ATILE_B + 2 * BTILE_B;  // 64 KB
    cudaFuncSetAttribute(fused_gemm, cudaFuncAttributeMaxDynamicSharedMemorySize,
                         smem_bytes);

    int grid = (Brows + 127) / 128;
    fused_gemm<<<grid, 256, smem_bytes>>>(x, fc1_b, fc2_w, fc2_b, out, Brows);
}